// round 16
// baseline (speedup 1.0000x reference)
#include <cuda_runtime.h>
#include <cuda_fp16.h>

// Problem constants (fixed by setup_inputs): N=50000, E=800000, F=64, U=64, H=8
#define Fd   64
#define Hh   8
#define HU   512          // H * U
#define NMAX 50000
#define EMAX 800000
#define CHUNK 64          // edges per warp in k_edge

// ---------------- static scratch (no allocations allowed) ----------------
__device__ __align__(16) __half d_g[(size_t)NMAX * HU];   // g fp16 (~51 MB)
__device__ __align__(16) uint2  d_x16[(size_t)NMAX * 16]; // X in fp16 (4 halves per uint2)
__device__ __align__(16) uint2  d_Cfrag[4 * 64 * 32];     // B fragments, 64 KB (kt, nt, lane)
__device__ float d_asrc[NMAX * Hh];
__device__ float d_adst[NMAX * Hh];
__device__ __align__(16) float d_asum[NMAX * Hh];         // per (src,h) attention sums
__device__ __align__(16) float d_oacc[(size_t)NMAX * Fd]; // pre-leaky output accumulator
__device__ float d_wa[2 * Hh * Fd];                       // folded attention vectors

__device__ __forceinline__ float leaky(float v) { return v >= 0.f ? v : 0.2f * v; }

__device__ __forceinline__ void mma16816(float* c, unsigned a0, unsigned a1,
                                         unsigned a2, unsigned a3,
                                         unsigned b0, unsigned b1) {
    asm volatile(
        "mma.sync.aligned.m16n8k16.row.col.f32.f16.f16.f32 "
        "{%0,%1,%2,%3}, {%4,%5,%6,%7}, {%8,%9}, {%0,%1,%2,%3};\n"
        : "+f"(c[0]), "+f"(c[1]), "+f"(c[2]), "+f"(c[3])
        : "r"(a0), "r"(a1), "r"(a2), "r"(a3), "r"(b0), "r"(b1));
}

// packed fp32x2 helpers (bit-exact pairs of IEEE fp32 FMA)
__device__ __forceinline__ unsigned long long pack2(float a, float b) {
    unsigned long long r;
    asm("mov.b64 %0, {%1, %2};" : "=l"(r) : "f"(a), "f"(b));
    return r;
}
__device__ __forceinline__ void unpack2(unsigned long long v, float& a, float& b) {
    asm("mov.b64 {%0, %1}, %2;" : "=f"(a), "=f"(b) : "l"(v));
}
__device__ __forceinline__ void fma2(unsigned long long& d, unsigned long long a,
                                     unsigned long long b) {
    asm("fma.rn.f32x2 %0, %1, %2, %0;" : "+l"(d) : "l"(a), "l"(b));
}
__device__ __forceinline__ unsigned long long h2f2(unsigned h2) {
    float2 f = __half22float2(*(__half2*)&h2);
    return pack2(f.x, f.y);
}

// ---------------- K0: fold weights into B-fragments + wa; x->fp16; zero accums -----
__global__ void k_prep(const float* __restrict__ W, const float* __restrict__ a,
                       const float* __restrict__ M, const float* __restrict__ x, int N) {
    int idx = blockIdx.x * blockDim.x + threadIdx.x;
    int nthr = gridDim.x * blockDim.x;

    if (idx < 4 * 64 * 32) {
        int kt = idx >> 11, rem = idx & 2047;
        int nt = rem >> 5, lane = rem & 31;
        int p = lane & 3, q = lane >> 2;
        int n = nt * 8 + q;
        int h = n >> 6, j = n & 63;
        int f0 = kt * 16 + p * 2;
        float c4[4];
#pragma unroll
        for (int k = 0; k < 4; ++k) {
            int f = f0 + (k >> 1) * 8 + (k & 1);
            const float* Wp = W + (h * Fd + f) * 64;
            const float* Mp = M + h * 64 * 64 + j;
            float s = 0.f;
#pragma unroll 8
            for (int u = 0; u < 64; ++u) s += __ldg(Wp + u) * __ldg(Mp + u * 64);
            c4[k] = s;
        }
        __half2 lo = __floats2half2_rn(c4[0], c4[1]);
        __half2 hi = __floats2half2_rn(c4[2], c4[3]);
        uint2 v;
        v.x = *(unsigned*)&lo;
        v.y = *(unsigned*)&hi;
        d_Cfrag[idx] = v;
    }
    if (idx < 2 * Hh * Fd) {                        // 1024 entries
        int which = idx >> 9;
        int r = idx & 511;
        int h = r >> 6, f = r & 63;
        const float* Wp = W + (h * Fd + f) * 64;
        const float* ap = a + h * 128 + which * 64;
        float s = 0.f;
#pragma unroll 8
        for (int u = 0; u < 64; ++u) s += __ldg(Wp + u) * __ldg(ap + u);
        d_wa[idx] = s;
    }

    // x -> fp16 (grid-strided)
    int total4 = N * 16;
    for (int i = idx; i < total4; i += nthr) {
        float4 v = __ldg((const float4*)x + i);
        __half2 lo = __floats2half2_rn(v.x, v.y);
        __half2 hi = __floats2half2_rn(v.z, v.w);
        uint2 u;
        u.x = *(unsigned*)&lo;
        u.y = *(unsigned*)&hi;
        d_x16[i] = u;
    }

    // zero accumulators
    float4 z = make_float4(0.f, 0.f, 0.f, 0.f);
    int n_oacc4 = N * Fd / 4;
    for (int i = idx; i < n_oacc4; i += nthr) ((float4*)d_oacc)[i] = z;
    int n_asum4 = N * Hh / 4;
    for (int i = idx; i < n_asum4; i += nthr) ((float4*)d_asum)[i] = z;
}

// ---------------- K1: g = X @ C tensor cores + alpha tail (y==0 blocks) ------------
// grid = (ceil(N/64), 4). MMA part identical to the 31.3us-measured version.
// Tail (blockIdx.y==0): compute alpha_src/adst for the block's 64 nodes from
// fp32 x staged in the freed 'so' smem (pitch 68: conflict-free broadcast).
__global__ void __launch_bounds__(256) k_mma(const float* __restrict__ x, int N) {
    __shared__ unsigned sx[64][36];     // 9216 B
    __shared__ unsigned so[64][68];     // 17408 B
    int tid = threadIdx.x;
    int warp = tid >> 5, lane = tid & 31;
    int p = lane & 3, q = lane >> 2;
    int rblk = blockIdx.x * 64;

    // stage x fp16 (coalesced global reads)
    const unsigned* xu = (const unsigned*)d_x16;   // 32 words per row
    for (int i = tid; i < 2048; i += 256) {
        int row = i >> 5, c = i & 31;
        int gr = min(rblk + row, N - 1);
        sx[row][c] = xu[(size_t)gr * 32 + c];
    }
    __syncthreads();

    int r0 = (warp >> 1) * 16;                     // local row base
    int nt0 = (warp & 1) * 8;                      // local n8-tile base (of 16)
    int ntg = blockIdx.y * 16 + nt0;               // global n8-tile base

    float acc[8][4];
#pragma unroll
    for (int t = 0; t < 8; ++t) {
        acc[t][0] = 0.f; acc[t][1] = 0.f; acc[t][2] = 0.f; acc[t][3] = 0.f;
    }

#pragma unroll
    for (int kt = 0; kt < 4; ++kt) {
        unsigned a0 = sx[r0 + q][kt * 8 + p];
        unsigned a1 = sx[r0 + q + 8][kt * 8 + p];
        unsigned a2 = sx[r0 + q][kt * 8 + p + 4];
        unsigned a3 = sx[r0 + q + 8][kt * 8 + p + 4];
        const uint2* bf = d_Cfrag + (kt * 64 + ntg) * 32 + lane;
#pragma unroll
        for (int nt = 0; nt < 8; ++nt) {
            uint2 b = __ldg(bf + nt * 32);
            mma16816(acc[nt], a0, a1, a2, a3, b.x, b.y);
        }
    }

    // stage output fragments to smem (conflict-free: bank = 4q+p+const)
#pragma unroll
    for (int nt = 0; nt < 8; ++nt) {
        int c = (nt0 + nt) * 4 + p;                // half2 col within 64
        __half2 h01 = __floats2half2_rn(acc[nt][0], acc[nt][1]);
        __half2 h23 = __floats2half2_rn(acc[nt][2], acc[nt][3]);
        so[r0 + q][c] = *(unsigned*)&h01;
        so[r0 + q + 8][c] = *(unsigned*)&h23;
    }
    __syncthreads();

    // coalesced STG.128 of the 64 x 128-col tile
    uint4* g4 = (uint4*)d_g;                       // 64 uint4 per row
    for (int i = tid; i < 1024; i += 256) {
        int row = i >> 4, c4 = i & 15;
        int gr = rblk + row;
        if (gr < N) {
            uint4 v = *(const uint4*)&so[row][c4 * 4];
            g4[(size_t)gr * 64 + blockIdx.y * 16 + c4] = v;
        }
    }

    // ---------- alpha tail (fp32, y==0 blocks only) ----------
    if (blockIdx.y == 0) {
        __syncthreads();                           // so+sx free for reuse
        float* sxf  = (float*)&so[0][0];           // x fp32, pitch 68
        float* swaf = (float*)&sx[0][0];           // wa, pitch 65 (16 rows)
        for (int i = tid; i < 64 * 64; i += 256) {
            int row = i >> 6, col = i & 63;
            int gr = rblk + row;
            sxf[row * 68 + col] = (gr < N) ? __ldg(x + (size_t)gr * 64 + col) : 0.f;
        }
        for (int i = tid; i < 1024; i += 256)
            swaf[(i >> 6) * 65 + (i & 63)] = d_wa[i];
        __syncthreads();

        int ln = tid >> 2;                         // local node
        int rbase = (tid & 3) * 4;                 // 4 outputs per thread
        int n = rblk + ln;
        if (n < N) {
            const float* xp = sxf + ln * 68;
#pragma unroll
            for (int j = 0; j < 4; ++j) {
                int r = rbase + j;
                const float* wap = swaf + r * 65;
                float s = 0.f;
#pragma unroll
                for (int u = 0; u < 64; ++u) s += xp[u] * wap[u];
                int which = r >> 3, h = r & 7;
                if (which) d_adst[n * 8 + h] = s;
                else       d_asrc[n * 8 + h] = s;
            }
        }
    }
}

// ---------------- K2: attention segment sums (8 edges/warp, loads front-loaded) ----
__global__ void k_att(const int* __restrict__ edges, int E) {
    int gw = (blockIdx.x * blockDim.x + threadIdx.x) >> 5;
    int lane = threadIdx.x & 31;
    int i = lane >> 3, h = lane & 7;
    int base = gw * 8;
    int e0 = base + i, e1 = base + 4 + i;
    bool v0 = e0 < E, v1 = e1 < E;

    int2 ed0 = make_int2(-1 - i, 0), ed1 = make_int2(-9 - i, 0);
    if (v0) ed0 = __ldg((const int2*)edges + e0);
    if (v1) ed1 = __ldg((const int2*)edges + e1);
    float as0 = v0 ? __ldg(d_asrc + ed0.x * 8 + h) : 0.f;
    float as1 = v1 ? __ldg(d_asrc + ed1.x * 8 + h) : 0.f;
    float ad0 = v0 ? __ldg(d_adst + ed0.y * 8 + h) : 0.f;
    float ad1 = v1 ? __ldg(d_adst + ed1.y * 8 + h) : 0.f;

    float att0 = 0.f, att1 = 0.f;
    if (v0) {
        float s = as0 + ad0;
        s = s >= 0.f ? s : 0.2f * s;
        s = fminf(2.f, fmaxf(-2.f, s));
        att0 = __expf(s);
    }
    if (v1) {
        float s = as1 + ad1;
        s = s >= 0.f ? s : 0.2f * s;
        s = fminf(2.f, fmaxf(-2.f, s));
        att1 = __expf(s);
    }

    unsigned full = 0xffffffffu;
    {
        int   s1 = __shfl_down_sync(full, ed0.x, 8);
        float q1 = __shfl_down_sync(full, att0, 8);
        float w1 = att0 + ((i < 3 && s1 == ed0.x) ? q1 : 0.f);
        int   s2 = __shfl_down_sync(full, ed0.x, 16);
        float q2 = __shfl_down_sync(full, w1, 16);
        float w2 = w1 + ((i < 2 && s2 == ed0.x) ? q2 : 0.f);
        int sp = __shfl_up_sync(full, ed0.x, 8);
        bool head = (i == 0) || (sp != ed0.x);
        if (v0 && head) atomicAdd(&d_asum[ed0.x * 8 + h], w2);
    }
    {
        int   s1 = __shfl_down_sync(full, ed1.x, 8);
        float q1 = __shfl_down_sync(full, att1, 8);
        float w1 = att1 + ((i < 3 && s1 == ed1.x) ? q1 : 0.f);
        int   s2 = __shfl_down_sync(full, ed1.x, 16);
        float q2 = __shfl_down_sync(full, w1, 16);
        float w2 = w1 + ((i < 2 && s2 == ed1.x) ? q2 : 0.f);
        int sp = __shfl_up_sync(full, ed1.x, 8);
        bool head = (i == 0) || (sp != ed1.x);
        if (v1 && head) atomicAdd(&d_asum[ed1.x * 8 + h], w2);
    }
}

// ---------------- K3: edge aggregation, uint4 g loads, f32x2 FMA --------------------
// Lane layout: load i (0/1) gives lane cols (i*32+lane)*8: head = i*4 + (lane>>3),
// j-block = (lane&7)*8. acc = 4 x f32x2 (8 floats). FMA slots halved vs scalar.
__global__ void k_edge(const int* __restrict__ edges, int E) {
    int gw = (blockIdx.x * blockDim.x + threadIdx.x) >> 5;
    int lane = threadIdx.x & 31;
    int e0 = gw * CHUNK;
    if (e0 >= E) return;
    int e1 = min(e0 + CHUNK, E);

    const uint4* __restrict__ gb = (const uint4*)d_g;     // 64 uint4 per row
    unsigned long long acc2[4] = {0ull, 0ull, 0ull, 0ull};
    float rs = 0.f, asrcv = 0.f;
    int cur = -1;
    unsigned full = 0xffffffffu;
    int hA = lane >> 3;                           // head for load 0; load 1 -> hA+4

    for (int e = e0; e < e1; e += 2) {
        bool hasB = (e + 1 < e1);
        int2 edA = __ldg((const int2*)edges + e);
        int2 edB = hasB ? __ldg((const int2*)edges + (e + 1)) : edA;
        float adA = (lane < 8) ? __ldg(d_adst + edA.y * 8 + lane) : 0.f;
        float adB = (lane < 8) ? __ldg(d_adst + edB.y * 8 + lane) : 0.f;

        uint4 gA0 = __ldg(gb + (size_t)edA.y * 64 + lane);
        uint4 gA1 = __ldg(gb + (size_t)edA.y * 64 + 32 + lane);
        uint4 gB0 = __ldg(gb + (size_t)edB.y * 64 + lane);
        uint4 gB1 = __ldg(gb + (size_t)edB.y * 64 + 32 + lane);

        // ---- edge A ----
        if (edA.x != cur) {                        // warp-uniform
            if (cur >= 0) {
                float af[8];
#pragma unroll
                for (int k = 0; k < 4; ++k) unpack2(acc2[k], af[2 * k], af[2 * k + 1]);
#pragma unroll
                for (int k = 0; k < 8; ++k) af[k] += __shfl_down_sync(full, af[k], 8);
#pragma unroll
                for (int k = 0; k < 8; ++k) af[k] += __shfl_down_sync(full, af[k], 16);
                if (lane < 8) {
#pragma unroll
                    for (int k = 0; k < 8; ++k)
                        atomicAdd(&d_oacc[(size_t)cur * 64 + lane * 8 + k], af[k]);
                }
#pragma unroll
                for (int k = 0; k < 4; ++k) acc2[k] = 0ull;
            }
            cur = edA.x;
            if (lane < 8) {
                asrcv = __ldg(d_asrc + cur * 8 + lane);
                rs = 1.f / __ldg(d_asum + cur * 8 + lane);
            }
        }
        {
            float wl = 0.f;
            if (lane < 8) {
                float s = asrcv + adA;
                s = s >= 0.f ? s : 0.2f * s;
                s = fminf(2.f, fmaxf(-2.f, s));
                wl = __expf(s) * rs;
            }
            float w0 = __shfl_sync(full, wl, hA);
            float w1 = __shfl_sync(full, wl, hA + 4);
            unsigned long long w0p = pack2(w0, w0), w1p = pack2(w1, w1);
            fma2(acc2[0], w0p, h2f2(gA0.x));
            fma2(acc2[1], w0p, h2f2(gA0.y));
            fma2(acc2[2], w0p, h2f2(gA0.z));
            fma2(acc2[3], w0p, h2f2(gA0.w));
            fma2(acc2[0], w1p, h2f2(gA1.x));
            fma2(acc2[1], w1p, h2f2(gA1.y));
            fma2(acc2[2], w1p, h2f2(gA1.z));
            fma2(acc2[3], w1p, h2f2(gA1.w));
        }

        // ---- edge B ----
        if (hasB) {
            if (edB.x != cur) {
                if (cur >= 0) {
                    float af[8];
#pragma unroll
                    for (int k = 0; k < 4; ++k) unpack2(acc2[k], af[2 * k], af[2 * k + 1]);
#pragma unroll
                    for (int k = 0; k < 8; ++k) af[k] += __shfl_down_sync(full, af[k], 8);
#pragma unroll
                    for (int k = 0; k < 8; ++k) af[k] += __shfl_down_sync(full, af[k], 16);
                    if (lane < 8) {
#pragma unroll
                        for (int k = 0; k < 8; ++k)
                            atomicAdd(&d_oacc[(size_t)cur * 64 + lane * 8 + k], af[k]);
                    }
#pragma unroll
                    for (int k = 0; k < 4; ++k) acc2[k] = 0ull;
                }
                cur = edB.x;
                if (lane < 8) {
                    asrcv = __ldg(d_asrc + cur * 8 + lane);
                    rs = 1.f / __ldg(d_asum + cur * 8 + lane);
                }
            }
            float wl = 0.f;
            if (lane < 8) {
                float s = asrcv + adB;
                s = s >= 0.f ? s : 0.2f * s;
                s = fminf(2.f, fmaxf(-2.f, s));
                wl = __expf(s) * rs;
            }
            float w0 = __shfl_sync(full, wl, hA);
            float w1 = __shfl_sync(full, wl, hA + 4);
            unsigned long long w0p = pack2(w0, w0), w1p = pack2(w1, w1);
            fma2(acc2[0], w0p, h2f2(gB0.x));
            fma2(acc2[1], w0p, h2f2(gB0.y));
            fma2(acc2[2], w0p, h2f2(gB0.z));
            fma2(acc2[3], w0p, h2f2(gB0.w));
            fma2(acc2[0], w1p, h2f2(gB1.x));
            fma2(acc2[1], w1p, h2f2(gB1.y));
            fma2(acc2[2], w1p, h2f2(gB1.z));
            fma2(acc2[3], w1p, h2f2(gB1.w));
        }
    }
    if (cur >= 0) {
        float af[8];
#pragma unroll
        for (int k = 0; k < 4; ++k) unpack2(acc2[k], af[2 * k], af[2 * k + 1]);
#pragma unroll
        for (int k = 0; k < 8; ++k) af[k] += __shfl_down_sync(full, af[k], 8);
#pragma unroll
        for (int k = 0; k < 8; ++k) af[k] += __shfl_down_sync(full, af[k], 16);
        if (lane < 8) {
#pragma unroll
            for (int k = 0; k < 8; ++k)
                atomicAdd(&d_oacc[(size_t)cur * 64 + lane * 8 + k], af[k]);
        }
    }
}

// ---------------- K4: final leaky ----------------
__global__ void k_final(float* __restrict__ out, int total) {
    int i = blockIdx.x * blockDim.x + threadIdx.x;
    if (i < total) out[i] = leaky(d_oacc[i]);
}

// ---------------- launch ----------------
extern "C" void kernel_launch(void* const* d_in, const int* in_sizes, int n_in,
                              void* d_out, int out_size) {
    const float* x     = (const float*)d_in[0];
    const int*   edges = (const int*)  d_in[1];
    const float* W     = (const float*)d_in[2];
    const float* a     = (const float*)d_in[3];
    const float* M     = (const float*)d_in[4];
    float* out = (float*)d_out;

    int N = in_sizes[0] / Fd;
    int E = in_sizes[1] / 2;

    k_prep<<<256, 256>>>(W, a, M, x, N);                               // #1
    dim3 mg((N + 63) / 64, 4);
    k_mma<<<mg, 256>>>(x, N);                                          // #2 (mma+alpha)
    k_att<<<((E + 7) / 8 * 32 + 255) / 256, 256>>>(edges, E);          // #3
    int nwarps = (E + CHUNK - 1) / CHUNK;
    k_edge<<<(nwarps * 32 + 255) / 256, 256>>>(edges, E);              // #4 (ncu sample)
    k_final<<<(N * Fd + 255) / 256, 256>>>(out, N * Fd);               // #5
}